// round 16
// baseline (speedup 1.0000x reference)
#include <cuda_runtime.h>
#include <cuda_bf16.h>
#include <cstdint>

#define EDIM 256
#define NE 1024
#define HW 4096
#define N_TOK 65536
#define ZQ_ELEMS 16777216
#define OFF_LOSS 16777216
#define OFF_ZERO 16777217
#define OFF_IDX  16777218
#define MARGIN2 2.0f

typedef unsigned long long ull;

// -------------------- device globals --------------------
__device__ __nv_bfloat16 g_ch[NE * EDIM];    // codebook bf16
__device__ float g_cn[NE];                   // ||c||^2 fp32
__device__ unsigned short g_cand[N_TOK][8];  // candidate codes per token
__device__ unsigned char  g_ccnt[N_TOK];     // candidate count per token
__device__ int   g_idx[N_TOK];
__device__ float g_part[16384];

__device__ __forceinline__ unsigned fenc(float x){
    unsigned u = __float_as_uint(x);
    return (u & 0x80000000u) ? ~u : (u | 0x80000000u);
}
__device__ __forceinline__ float fdec(unsigned e){
    unsigned u = (e & 0x80000000u) ? (e & 0x7FFFFFFFu) : ~e;
    return __uint_as_float(u);
}

// mma.sync m16n8k16 bf16 -> f32 (Ampere-era PTX; valid on plain sm_103 target)
#define MMA16816(c, a, b) \
    asm volatile("mma.sync.aligned.m16n8k16.row.col.f32.bf16.bf16.f32 " \
        "{%0,%1,%2,%3}, {%4,%5,%6,%7}, {%8,%9}, {%0,%1,%2,%3};" \
        : "+f"((c)[0]), "+f"((c)[1]), "+f"((c)[2]), "+f"((c)[3]) \
        : "r"((a)[0]), "r"((a)[1]), "r"((a)[2]), "r"((a)[3]), \
          "r"((b)[0]), "r"((b)[1]))

// -------------------- smem layout for p1 (byte offsets) --------------------
// z/c tiles: row stride 264 bf16 = 528 B = 132 words
#define S3_ZH   0          // 64 x 528 = 33792
#define S3_CH   33792      // 64 x 528 = 33792
#define S3_TMIN 67584      // 64 x 4
#define S3_CNT  67840      // 64 x 4
#define S3_FLAG 68096      // 64 x 4
#define P3_SMEM 68352

// -------------------- kernel 1: codebook prep (bf16 + norms) --------------------
__global__ void prep_cb_kernel(const float* __restrict__ cb){
    __shared__ float red[256];
    int code = blockIdx.x, k = threadIdx.x;
    float v = cb[code * EDIM + k];
    g_ch[code * EDIM + k] = __float2bfloat16(v);
    red[k] = v * v;
    __syncthreads();
    for (int s = 128; s > 0; s >>= 1){
        if (k < s) red[k] += red[k + s];
        __syncthreads();
    }
    if (k == 0) g_cn[code] = red[0];
}

// -------------------- kernel 2: fused HMMA shortlist, register top-3 per slot ----------
// Block: 64 tokens x ALL 1024 codes (16 passes of 64). 8 warps = 4(M) x 2(N).
// dist~ = ||c||^2 - 2*(zh.ch)  (err <= ~0.3 abs; MARGIN2 = 2.0 >> 2*err)
// Each (token, wn, tig) slot keeps its top-3 smallest (dist,code) keys in registers.
// Exact block-min via atomicMin of slot minima. Emit slot entries <= min+MARGIN2;
// if a slot's 3rd-best qualifies -> token overflow -> exact full scan (sound).
// smem = 67 KB -> 2-3 blocks/SM (vs 1 before): latency overlap.
__global__ __launch_bounds__(256, 2)
void p1_kernel(const float* __restrict__ z){
    extern __shared__ char sm[];
    uint32_t* zh32 = (uint32_t*)(sm + S3_ZH);
    uint32_t* ch32 = (uint32_t*)(sm + S3_CH);
    unsigned* tmin = (unsigned*)(sm + S3_TMIN);
    unsigned* scnt = (unsigned*)(sm + S3_CNT);
    unsigned* sflg = (unsigned*)(sm + S3_FLAG);

    const int tid = threadIdx.x;
    const int lane = tid & 31, wid = tid >> 5;
    const int gid = lane >> 2, tig = lane & 3;
    const int wm = wid & 3, wn = wid >> 2;

    const int n0 = blockIdx.x << 6;
    const int b = n0 >> 12, hw0 = n0 & 4095;
    const float* zb = z + (size_t)b * (EDIM * HW) + hw0;

    if (tid < 64){ tmin[tid] = 0xFFFFFFFFu; scnt[tid] = 0; sflg[tid] = 0; }

    // build z bf16 tile [64 tok][256 k], stride 528 B
    for (int i = tid; i < 4096; i += 256){
        int k = i >> 4, t4 = (i & 15) << 2;
        float4 v = *(const float4*)(zb + (size_t)k * HW + t4);
        float vv[4] = {v.x, v.y, v.z, v.w};
        #pragma unroll
        for (int j = 0; j < 4; j++)
            *(__nv_bfloat16*)(sm + S3_ZH + (t4 + j) * 528 + k * 2) = __float2bfloat16(vv[j]);
    }

    ull top3[2][3];
    #pragma unroll
    for (int rp = 0; rp < 2; rp++)
        #pragma unroll
        for (int e = 0; e < 3; e++) top3[rp][e] = ~0ULL;

    for (int pass = 0; pass < 16; pass++){
        __syncthreads();
        {
            int row = tid >> 2, kc = (tid & 3) << 6;
            const uint4* sh = (const uint4*)(g_ch + (size_t)(pass * 64 + row) * EDIM + kc);
            uint4* dh = (uint4*)(sm + S3_CH + row * 528 + kc * 2);
            #pragma unroll
            for (int i = 0; i < 8; i++) dh[i] = sh[i];
        }
        __syncthreads();

        float acc[4][4];
        #pragma unroll
        for (int nt = 0; nt < 4; nt++)
            #pragma unroll
            for (int r = 0; r < 4; r++) acc[nt][r] = 0.0f;

        #pragma unroll 4
        for (int ks = 0; ks < 16; ks++){
            uint32_t ah[4];
            int r0 = (wm * 16 + gid) * 132 + ks * 8 + tig;
            ah[0] = zh32[r0];
            ah[1] = zh32[r0 + 8 * 132];
            ah[2] = zh32[r0 + 4];
            ah[3] = zh32[r0 + 8 * 132 + 4];
            uint32_t bh[4][2];
            #pragma unroll
            for (int nt = 0; nt < 4; nt++){
                int c0 = (wn * 32 + nt * 8 + gid) * 132 + ks * 8 + tig;
                bh[nt][0] = ch32[c0];
                bh[nt][1] = ch32[c0 + 4];
            }
            #pragma unroll
            for (int nt = 0; nt < 4; nt++)
                MMA16816(acc[nt], ah, bh[nt]);
        }

        // epilogue: insert this pass's 8 codes per slot into register top-3
        #pragma unroll
        for (int rp = 0; rp < 2; rp++){
            #pragma unroll
            for (int nt = 0; nt < 4; nt++){
                int code = pass * 64 + wn * 32 + nt * 8 + tig * 2;
                float d0 = __ldg(&g_cn[code])     - 2.0f * acc[nt][rp * 2];
                float d1 = __ldg(&g_cn[code + 1]) - 2.0f * acc[nt][rp * 2 + 1];
                ull k0 = ((ull)fenc(d0) << 32) | (unsigned)code;
                ull k1 = ((ull)fenc(d1) << 32) | (unsigned)(code + 1);
                #pragma unroll
                for (int s = 0; s < 2; s++){
                    ull key = s ? k1 : k0;
                    if (key < top3[rp][2]){
                        if (key < top3[rp][1]){
                            top3[rp][2] = top3[rp][1];
                            if (key < top3[rp][0]){
                                top3[rp][1] = top3[rp][0];
                                top3[rp][0] = key;
                            } else top3[rp][1] = key;
                        } else top3[rp][2] = key;
                    }
                }
            }
        }
    }

    // block-exact min of approx dists (slot top1s cover all codes)
    #pragma unroll
    for (int rp = 0; rp < 2; rp++){
        int tl = wm * 16 + gid + rp * 8;
        atomicMin(&tmin[tl], (unsigned)(top3[rp][0] >> 32));
    }
    __syncthreads();

    // emit candidates vs final-min threshold
    #pragma unroll
    for (int rp = 0; rp < 2; rp++){
        int tl = wm * 16 + gid + rp * 8;
        float thr = fdec(tmin[tl]) + MARGIN2;
        #pragma unroll
        for (int e = 0; e < 3; e++){
            ull key = top3[rp][e];
            if (key != ~0ULL && fdec((unsigned)(key >> 32)) <= thr){
                if (e == 2){ atomicOr(&sflg[tl], 1u); }       // 4th may be dropped
                else {
                    unsigned pos = atomicAdd(&scnt[tl], 1u);
                    if (pos < 8) g_cand[n0 + tl][pos] = (unsigned short)(key & 0xFFFFu);
                }
            }
        }
    }
    __syncthreads();

    if (tid < 64){
        unsigned c = scnt[tid];
        g_ccnt[n0 + tid] = sflg[tid] ? 255 : (unsigned char)(c > 255 ? 255 : c);
    }
}

// -------------------- kernel 3: exact fp32 rescore of candidates --------------------
// Block: 64 tokens, 4 threads/token. Same exact-score + tie-break as R1 (passed).
__global__ void rescore_kernel(const float* __restrict__ z, const float* __restrict__ cb,
                               float* __restrict__ out){
    extern __shared__ char smem_raw[];
    float* zs = (float*)smem_raw;              // [256 k][64 tok]
    ull* keys = (ull*)(smem_raw + 65536);      // [64]
    int tid = threadIdx.x;
    int n0 = blockIdx.x << 6;
    int b = n0 >> 12, hw0 = n0 & 4095;
    const float* zb = z + (size_t)b * (EDIM * HW) + hw0;

    for (int i = tid; i < 4096; i += 256){
        int k = i >> 4, t4 = (i & 15) << 2;
        float4 v = *(const float4*)(zb + (size_t)k * HW + t4);
        *(float4*)(zs + k * 64 + t4) = v;
    }
    if (tid < 64) keys[tid] = ~0ULL;
    __syncthreads();

    int lt = tid >> 2, sub = tid & 3, n = n0 + lt;
    int cnt = g_ccnt[n];
    bool ovf = (cnt > 8) || (cnt == 0);

    ull bk = ~0ULL;
    int m = ovf ? NE : cnt;
    for (int ci = sub; ci < m; ci += 4){
        int code = ovf ? ci : (int)g_cand[n][ci];
        const float4* crow = (const float4*)(cb + (size_t)code * EDIM);
        float acc = 0.0f;
        #pragma unroll 8
        for (int kk = 0; kk < 64; kk++){
            float4 cv = __ldg(crow + kk);
            int k = kk << 2;
            acc = fmaf(cv.x, zs[k * 64 + lt], acc);
            acc = fmaf(cv.y, zs[(k + 1) * 64 + lt], acc);
            acc = fmaf(cv.z, zs[(k + 2) * 64 + lt], acc);
            acc = fmaf(cv.w, zs[(k + 3) * 64 + lt], acc);
        }
        float dist = __ldg(&g_cn[code]) - 2.0f * acc;
        ull key = ((ull)fenc(dist) << 32) | (unsigned)code;
        if (key < bk) bk = key;
    }
    if (bk != ~0ULL) atomicMin(&keys[lt], bk);
    __syncthreads();
    if (tid < 64){
        int idx = (int)(unsigned)(keys[tid] & 0xFFFFFFFFULL);
        g_idx[n0 + tid] = idx;
        out[OFF_IDX + n0 + tid] = (float)idx;
    }
}

// -------------------- kernel 4: gather z_q + loss partials --------------------
__global__ void gather_kernel(const float* __restrict__ z, const float* __restrict__ cb,
                              float* __restrict__ out){
    __shared__ float red[8];
    int t = blockIdx.x * 256 + threadIdx.x;
    int o4 = t << 2;
    int b = o4 >> 20;
    int rem = o4 & 1048575;
    int c = rem >> 12;
    int hw = rem & 4095;
    int n = (b << 12) + hw;

    float4 zv = *(const float4*)(z + o4);
    int i0 = g_idx[n], i1 = g_idx[n + 1], i2 = g_idx[n + 2], i3 = g_idx[n + 3];
    float4 q;
    q.x = __ldg(cb + (size_t)i0 * EDIM + c);
    q.y = __ldg(cb + (size_t)i1 * EDIM + c);
    q.z = __ldg(cb + (size_t)i2 * EDIM + c);
    q.w = __ldg(cb + (size_t)i3 * EDIM + c);
    *(float4*)(out + o4) = q;

    float dx = q.x - zv.x, dy = q.y - zv.y, dz = q.z - zv.z, dw = q.w - zv.w;
    float s = dx * dx + dy * dy + dz * dz + dw * dw;

    #pragma unroll
    for (int off = 16; off; off >>= 1) s += __shfl_down_sync(0xffffffffu, s, off);
    int lane = threadIdx.x & 31, wid = threadIdx.x >> 5;
    if (lane == 0) red[wid] = s;
    __syncthreads();
    if (wid == 0){
        float v = (lane < 8) ? red[lane] : 0.0f;
        #pragma unroll
        for (int off = 4; off; off >>= 1) v += __shfl_down_sync(0xffffffffu, v, off);
        if (lane == 0) g_part[blockIdx.x] = v;
    }
}

// -------------------- kernel 5: deterministic final loss reduction --------------------
__global__ void finalize_kernel(float* __restrict__ out){
    __shared__ float red[256];
    int tid = threadIdx.x;
    float s = 0.0f;
    for (int j = 0; j < 64; j++) s += g_part[tid + (j << 8)];
    red[tid] = s;
    __syncthreads();
    for (int st = 128; st > 0; st >>= 1){
        if (tid < st) red[tid] += red[tid + st];
        __syncthreads();
    }
    if (tid == 0){
        out[OFF_LOSS] = red[0] / 16777216.0f;
        out[OFF_ZERO] = 0.0f;
    }
}

// -------------------- launch --------------------
extern "C" void kernel_launch(void* const* d_in, const int* in_sizes, int n_in,
                              void* d_out, int out_size){
    const float* z  = (const float*)d_in[0];
    const float* cb = (const float*)d_in[1];
    if (n_in >= 2 && in_sizes[0] == NE * EDIM && in_sizes[1] == ZQ_ELEMS){
        const float* t = z; z = cb; cb = t;
    }
    float* out = (float*)d_out;

    cudaFuncSetAttribute(p1_kernel, cudaFuncAttributeMaxDynamicSharedMemorySize, P3_SMEM);
    cudaFuncSetAttribute(rescore_kernel, cudaFuncAttributeMaxDynamicSharedMemorySize, 66048);

    prep_cb_kernel<<<NE, 256>>>(cb);
    p1_kernel<<<N_TOK / 64, 256, P3_SMEM>>>(z);
    rescore_kernel<<<N_TOK / 64, 256, 66048>>>(z, cb, out);
    gather_kernel<<<ZQ_ELEMS / 1024, 256>>>(z, cb, out);
    finalize_kernel<<<1, 256>>>(out);
}